// round 13
// baseline (speedup 1.0000x reference)
#include <cuda_runtime.h>
#include <cuda_bf16.h>
#include <cstdint>
#include <math.h>

// Problem dims (fixed)
#define BB 1024   // batch
#define SS 128    // seq len
#define VV 20000  // vocab
#define EE 512    // embed dim
#define HH 1024   // hidden
#define GG 4096   // 4*H (gates)
#define KTOT 1536 // E + H
#define NN 4096   // output dim

// Tiling (bf16: BK=64 elems per stage, mma.m16n8k16)
#define BM 128
#define BN 128
#define BK 64
#define NST 3
#define ROWB 144                          // bytes per smem tile row (128 data + 16 pad)
#define TILEB (128 * ROWB)                // 18432 B
#define STAGE (4 * TILEB)                 // Ah|Al|Bh|Bl = 73728 B
#define SMEM_TOTAL (NST * STAGE)          // 221184 B

typedef __nv_bfloat16 bf16;

// Scratch: everything pre-split into bf16 (hi, lo) pairs
__device__ bf16 g_tabh[(size_t)VV * EE];
__device__ bf16 g_tabl[(size_t)VV * EE];
__device__ bf16 g_wph[(size_t)GG * KTOT];
__device__ bf16 g_wpl[(size_t)GG * KTOT];
__device__ bf16 g_woh[(size_t)NN * HH];
__device__ bf16 g_wol[(size_t)NN * HH];
__device__ float g_biasp[GG];
__device__ bf16 g_hhiA[BB * HH];          // h ping-pong (intra-launch race fix)
__device__ bf16 g_hhiB[BB * HH];
__device__ bf16 g_hloA[BB * HH];
__device__ bf16 g_hloB[BB * HH];
__device__ float g_c[BB * HH];

// ---------------------------------------------------------------------------
__device__ __forceinline__ uint32_t smem_u32(const void* p) {
    uint32_t a;
    asm("{ .reg .u64 t; cvta.to.shared.u64 t, %1; cvt.u32.u64 %0, t; }" : "=r"(a) : "l"(p));
    return a;
}
#define CP16(dst, src) \
    asm volatile("cp.async.cg.shared.global [%0], [%1], 16;" :: "r"(dst), "l"(src))
#define CP_COMMIT() asm volatile("cp.async.commit_group;" ::: "memory")
#define CP_WAIT2()  asm volatile("cp.async.wait_group 2;" ::: "memory")

__device__ __forceinline__ void ldsm4(uint32_t& r0, uint32_t& r1, uint32_t& r2,
                                      uint32_t& r3, uint32_t addr) {
    asm volatile("ldmatrix.sync.aligned.m8n8.x4.shared.b16 {%0,%1,%2,%3}, [%4];"
                 : "=r"(r0), "=r"(r1), "=r"(r2), "=r"(r3) : "r"(addr));
}
__device__ __forceinline__ void ldsm2(uint32_t& r0, uint32_t& r1, uint32_t addr) {
    asm volatile("ldmatrix.sync.aligned.m8n8.x2.shared.b16 {%0,%1}, [%2];"
                 : "=r"(r0), "=r"(r1) : "r"(addr));
}
__device__ __forceinline__ void mma_bf16(float* c, const uint32_t* a, const uint32_t* b) {
    asm volatile(
        "mma.sync.aligned.m16n8k16.row.col.f32.bf16.bf16.f32 "
        "{%0,%1,%2,%3}, {%4,%5,%6,%7}, {%8,%9}, {%0,%1,%2,%3};"
        : "+f"(c[0]), "+f"(c[1]), "+f"(c[2]), "+f"(c[3])
        : "r"(a[0]), "r"(a[1]), "r"(a[2]), "r"(a[3]), "r"(b[0]), "r"(b[1]));
}
__device__ __forceinline__ float fsigmoid(float x) { return 1.0f / (1.0f + expf(-x)); }

// split x into bf16 hi + bf16 lo (≈16 mantissa bits total)
__device__ __forceinline__ void bsplit(float x, bf16& h, bf16& l) {
    h = __float2bfloat16(x);
    l = __float2bfloat16(x - __bfloat162float(h));
}

// ---------------------------------------------------------------------------
// Prep kernels (ordered so positions 4+ in the launch stream are lstm_gemm:
// splitTab(1), permW(2), zero+permB fused(3), then 128x lstm_gemm, splitWout, out)
// ---------------------------------------------------------------------------
__global__ void splitTab_kernel(const float* __restrict__ tab) {
    int v = blockIdx.x;
    const float4* s = (const float4*)(tab + (size_t)v * EE);
    float4 val = s[threadIdx.x];
    size_t d = (size_t)v * EE + threadIdx.x * 4;
    bsplit(val.x, g_tabh[d + 0], g_tabl[d + 0]);
    bsplit(val.y, g_tabh[d + 1], g_tabl[d + 1]);
    bsplit(val.z, g_tabh[d + 2], g_tabl[d + 2]);
    bsplit(val.w, g_tabh[d + 3], g_tabl[d + 3]);
}
// Wp[4u+g, :] = [W_ih[g*H+u, :] | W_hh[g*H+u, :]], split bf16 hi/lo
__global__ void permW_kernel(const float* __restrict__ Wih, const float* __restrict__ Whh) {
    int n = blockIdx.x;
    int u = n >> 2, g = n & 3;
    int sr = g * HH + u;
    const float4* s1 = (const float4*)(Wih + (size_t)sr * EE);
    const float4* s2 = (const float4*)(Whh + (size_t)sr * HH);
    size_t base = (size_t)n * KTOT;
    float4 v;
    v = s1[threadIdx.x];
    {   size_t d = base + threadIdx.x * 4;
        bsplit(v.x, g_wph[d+0], g_wpl[d+0]); bsplit(v.y, g_wph[d+1], g_wpl[d+1]);
        bsplit(v.z, g_wph[d+2], g_wpl[d+2]); bsplit(v.w, g_wph[d+3], g_wpl[d+3]); }
    v = s2[threadIdx.x];
    {   size_t d = base + EE + threadIdx.x * 4;
        bsplit(v.x, g_wph[d+0], g_wpl[d+0]); bsplit(v.y, g_wph[d+1], g_wpl[d+1]);
        bsplit(v.z, g_wph[d+2], g_wpl[d+2]); bsplit(v.w, g_wph[d+3], g_wpl[d+3]); }
    v = s2[128 + threadIdx.x];
    {   size_t d = base + EE + 512 + threadIdx.x * 4;
        bsplit(v.x, g_wph[d+0], g_wpl[d+0]); bsplit(v.y, g_wph[d+1], g_wpl[d+1]);
        bsplit(v.z, g_wph[d+2], g_wpl[d+2]); bsplit(v.w, g_wph[d+3], g_wpl[d+3]); }
}
// fused: zero h/c buffers + permuted bias (grid = BB*HH/256 blocks; first 16 do bias)
__global__ void zeroPermB_kernel(const float* __restrict__ bih, const float* __restrict__ bhh) {
    int i = blockIdx.x * blockDim.x + threadIdx.x;
    bf16 z = __float2bfloat16(0.0f);
    g_hhiA[i] = z; g_hhiB[i] = z; g_hloA[i] = z; g_hloB[i] = z;
    g_c[i] = 0.0f;
    if (i < GG) {
        int u = i >> 2, g = i & 3;
        int sr = g * HH + u;
        g_biasp[i] = bih[sr] + bhh[sr];
    }
}
__global__ void splitWout_kernel(const float* __restrict__ Wout) {
    int n = blockIdx.x;
    const float4* s = (const float4*)(Wout + (size_t)n * HH);
    size_t base = (size_t)n * HH;
#pragma unroll
    for (int seg = 0; seg < 2; seg++) {
        float4 v = s[seg * 128 + threadIdx.x];
        size_t d = base + (seg * 128 + threadIdx.x) * 4;
        bsplit(v.x, g_woh[d+0], g_wol[d+0]); bsplit(v.y, g_woh[d+1], g_wol[d+1]);
        bsplit(v.z, g_woh[d+2], g_wol[d+2]); bsplit(v.w, g_woh[d+3], g_wol[d+3]);
    }
}

// ---------------------------------------------------------------------------
// bf16x3 mma.sync GEMM: C = A*B^T with A,B as (hi,lo) bf16 pairs.
// CELL=true: A = [emb(m[b,s]) | hIn] (gather fused), LSTM epilogue -> hOut, c.
//            ping-pong h buffers (race fix). CELL=false: plain bias+store.
// ---------------------------------------------------------------------------
template <bool CELL>
__global__ __launch_bounds__(256, 1) void lstm_gemm(
    const int* __restrict__ mPtr, int sStep,
    const bf16* __restrict__ tabh, const bf16* __restrict__ tabl,
    const bf16* __restrict__ A1h, const bf16* __restrict__ A1l, int lda,
    const bf16* __restrict__ Bh,  const bf16* __restrict__ Bl,  int ldb,
    int nIter,
    const float* __restrict__ bias,
    const bf16* __restrict__ hInHi, const bf16* __restrict__ hInLo,
    bf16* __restrict__ hOutHi, bf16* __restrict__ hOutLo,
    float* __restrict__ cPtr,
    float* __restrict__ out)
{
    extern __shared__ __align__(16) char smem[];
    __shared__ int msm[BM];
    const uint32_t sb = smem_u32(smem);
    const int tid  = threadIdx.x;
    const int wid  = tid >> 5, lane = tid & 31;
    const int wm   = wid >> 2;            // 0..1
    const int wn   = wid & 3;             // 0..3
    const int row0 = blockIdx.y * BM;
    const int col0 = blockIdx.x * BN;

    if (CELL) {
        if (tid < BM) msm[tid] = mPtr[(size_t)(row0 + tid) * SS + sStep];
        __syncthreads();
    }

    float acc[4][4][4];
#pragma unroll
    for (int i = 0; i < 4; i++)
#pragma unroll
        for (int j = 0; j < 4; j++)
#pragma unroll
            for (int r = 0; r < 4; r++) acc[i][j][r] = 0.0f;

    // stage layout: [Ah | Al | Bh | Bl], each 128 rows x 144B (64 bf16 + pad)
    auto load_stage = [&](int slot, int k0) {
        const uint32_t ah = sb + slot * STAGE;
        const uint32_t al = ah + TILEB;
        const uint32_t bh = al + TILEB;
        const uint32_t bl = bh + TILEB;
#pragma unroll
        for (int j = 0; j < 4; j++) {
            int cidx = tid + j * 256;      // 0..1023 : 128 rows x 8 chunks
            int r = cidx >> 3, q = cidx & 7;
            uint32_t soff = (uint32_t)(r * ROWB + q * 16);
            if (CELL) {
                if (k0 < EE) {             // embedding columns: gather from table
                    size_t goff = (size_t)msm[r] * EE + k0 + q * 8;
                    CP16(ah + soff, tabh + goff);
                    CP16(al + soff, tabl + goff);
                } else {                   // hidden columns (previous step's h)
                    size_t goff = (size_t)(row0 + r) * HH + (k0 - EE) + q * 8;
                    CP16(ah + soff, hInHi + goff);
                    CP16(al + soff, hInLo + goff);
                }
            } else {
                size_t goff = (size_t)(row0 + r) * lda + k0 + q * 8;
                CP16(ah + soff, A1h + goff);
                CP16(al + soff, A1l + goff);
            }
        }
#pragma unroll
        for (int j = 0; j < 4; j++) {
            int cidx = tid + j * 256;
            int r = cidx >> 3, q = cidx & 7;
            uint32_t soff = (uint32_t)(r * ROWB + q * 16);
            size_t goff = (size_t)(col0 + r) * ldb + k0 + q * 8;
            CP16(bh + soff, Bh + goff);
            CP16(bl + soff, Bl + goff);
        }
    };

    auto compute = [&](int slot) {
        const uint32_t ah = sb + slot * STAGE;
        const uint32_t al = ah + TILEB;
        const uint32_t bh = al + TILEB;
        const uint32_t bl = bh + TILEB;
        const int arow  = wm * 64 + (lane & 15);
        const int acolB = (lane >> 4) * 16;          // byte offset of k-half
        const int brow  = wn * 32 + (lane & 7);
        const int bcolB = ((lane >> 3) & 1) * 16;
#pragma unroll
        for (int ks = 0; ks < 4; ks++) {             // 4 x k16 per BK=64 stage
            const int kB = ks * 32;                  // 16 bf16 = 32 bytes
            uint32_t afh[4][4], afl[4][4], bfh[4][2], bfl[4][2];
#pragma unroll
            for (int mt = 0; mt < 4; mt++) {
                uint32_t off = (uint32_t)((arow + mt * 16) * ROWB + acolB + kB);
                ldsm4(afh[mt][0], afh[mt][1], afh[mt][2], afh[mt][3], ah + off);
                ldsm4(afl[mt][0], afl[mt][1], afl[mt][2], afl[mt][3], al + off);
            }
#pragma unroll
            for (int nt = 0; nt < 4; nt++) {
                uint32_t off = (uint32_t)((brow + nt * 8) * ROWB + bcolB + kB);
                ldsm2(bfh[nt][0], bfh[nt][1], bh + off);
                ldsm2(bfl[nt][0], bfl[nt][1], bl + off);
            }
#pragma unroll
            for (int mt = 0; mt < 4; mt++)
#pragma unroll
                for (int nt = 0; nt < 4; nt++) {
                    mma_bf16(acc[mt][nt], afh[mt], bfh[nt]);   // hi*hi
                    mma_bf16(acc[mt][nt], afl[mt], bfh[nt]);   // lo*hi
                    mma_bf16(acc[mt][nt], afh[mt], bfl[nt]);   // hi*lo
                }
        }
    };

    load_stage(0, 0); CP_COMMIT();
    if (nIter > 1) load_stage(1, BK);
    CP_COMMIT();
    for (int it = 0; it < nIter; ++it) {
        if (it + 2 < nIter) load_stage((it + 2) % NST, (it + 2) * BK);
        CP_COMMIT();
        CP_WAIT2();
        __syncthreads();
        compute(it % NST);
        __syncthreads();
    }

    if (CELL) {
        // single-pass epilogue: all 8 warps stage acc into [128][132] floats (67.5KB)
        float* gsm = (float*)smem;
        const int h0 = col0 >> 2;
#pragma unroll
        for (int mt = 0; mt < 4; mt++) {
            const int lr = wm * 64 + mt * 16 + (lane >> 2);
#pragma unroll
            for (int nt = 0; nt < 4; nt++) {
                const int cc = wn * 32 + nt * 8 + 2 * (lane & 3);
                float2 v0 = {acc[mt][nt][0], acc[mt][nt][1]};
                float2 v1 = {acc[mt][nt][2], acc[mt][nt][3]};
                *(float2*)&gsm[lr * 132 + cc]       = v0;
                *(float2*)&gsm[(lr + 8) * 132 + cc] = v1;
            }
        }
        __syncthreads();
#pragma unroll
        for (int j = 0; j < 16; j++) {
            const int idx = tid + j * 256;     // 0..4095 = 128 rows x 32 units
            const int lr = idx >> 5, u = idx & 31;
            const float4 g  = *(const float4*)&gsm[lr * 132 + 4 * u];
            const float4 bv = *(const float4*)&bias[col0 + 4 * u];
            const int grow = row0 + lr;
            const size_t off = (size_t)grow * HH + h0 + u;
            const float co = cPtr[off];
            const float gi = fsigmoid(g.x + bv.x);
            const float gf = fsigmoid(g.y + bv.y);
            const float gg = tanhf(g.z + bv.z);
            const float go = fsigmoid(g.w + bv.w);
            const float cn = gf * co + gi * gg;
            const float hn = go * tanhf(cn);
            cPtr[off] = cn;
            bf16 hb = __float2bfloat16(hn);
            hOutHi[off] = hb;
            hOutLo[off] = __float2bfloat16(hn - __bfloat162float(hb));
        }
    } else {
#pragma unroll
        for (int mt = 0; mt < 4; mt++) {
            const int rr = row0 + wm * 64 + mt * 16 + (lane >> 2);
#pragma unroll
            for (int nt = 0; nt < 4; nt++) {
                const int cc = col0 + wn * 32 + nt * 8 + 2 * (lane & 3);
                float2 v0 = {acc[mt][nt][0] + bias[cc], acc[mt][nt][1] + bias[cc + 1]};
                float2 v1 = {acc[mt][nt][2] + bias[cc], acc[mt][nt][3] + bias[cc + 1]};
                *(float2*)(out + (size_t)rr * NN + cc)       = v0;
                *(float2*)(out + (size_t)(rr + 8) * NN + cc) = v1;
            }
        }
    }
}

// ---------------------------------------------------------------------------
extern "C" void kernel_launch(void* const* d_in, const int* in_sizes, int n_in,
                              void* d_out, int out_size) {
    const int*   m     = (const int*)d_in[0];
    const float* tab   = (const float*)d_in[1];
    const float* W_ih  = (const float*)d_in[2];
    const float* W_hh  = (const float*)d_in[3];
    const float* b_ih  = (const float*)d_in[4];
    const float* b_hh  = (const float*)d_in[5];
    const float* W_out = (const float*)d_in[6];
    const float* b_out = (const float*)d_in[7];
    float* out = (float*)d_out;

    bf16 *tabh, *tabl, *wph, *wpl, *woh, *wol;
    float *biasp, *c;
    bf16 *hhi[2], *hlo[2];
    cudaGetSymbolAddress((void**)&tabh,    g_tabh);
    cudaGetSymbolAddress((void**)&tabl,    g_tabl);
    cudaGetSymbolAddress((void**)&wph,     g_wph);
    cudaGetSymbolAddress((void**)&wpl,     g_wpl);
    cudaGetSymbolAddress((void**)&woh,     g_woh);
    cudaGetSymbolAddress((void**)&wol,     g_wol);
    cudaGetSymbolAddress((void**)&biasp,   g_biasp);
    cudaGetSymbolAddress((void**)&hhi[0],  g_hhiA);
    cudaGetSymbolAddress((void**)&hhi[1],  g_hhiB);
    cudaGetSymbolAddress((void**)&hlo[0],  g_hloA);
    cudaGetSymbolAddress((void**)&hlo[1],  g_hloB);
    cudaGetSymbolAddress((void**)&c,       g_c);

    cudaFuncSetAttribute(lstm_gemm<true>,  cudaFuncAttributeMaxDynamicSharedMemorySize, SMEM_TOTAL);
    cudaFuncSetAttribute(lstm_gemm<false>, cudaFuncAttributeMaxDynamicSharedMemorySize, SMEM_TOTAL);

    // prep: exactly 3 launches before the mainloop so ncu (-s N) lands on lstm_gemm
    splitTab_kernel<<<VV, 128>>>(tab);
    permW_kernel<<<GG, 128>>>(W_ih, W_hh);
    zeroPermB_kernel<<<(BB * HH) / 256, 256>>>(b_ih, b_hh);

    dim3 grid(NN / BN, BB / BM);   // (32, 8)
    for (int s = 0; s < SS; s++) {
        const int rd = s & 1, wr = (s + 1) & 1;   // ping-pong h (race fix)
        lstm_gemm<true><<<grid, 256, SMEM_TOTAL>>>(
            m, s, tabh, tabl,
            nullptr, nullptr, 0,
            wph, wpl, KTOT,
            KTOT / BK,              // 24 iters
            biasp,
            hhi[rd], hlo[rd],       // read h_s
            hhi[wr], hlo[wr],       // write h_{s+1}
            c, nullptr);
    }
    // W_out split only needed now
    splitWout_kernel<<<NN, 128>>>(W_out);
    // after 128 steps (even), final h is in buffer 0
    lstm_gemm<false><<<grid, 256, SMEM_TOTAL>>>(
        nullptr, 0, nullptr, nullptr,
        hhi[0], hlo[0], HH,
        woh, wol, HH,
        HH / BK,                    // 16 iters
        b_out,
        nullptr, nullptr, nullptr, nullptr, nullptr, out);
}

// round 14
// speedup vs baseline: 1.1336x; 1.1336x over previous
#include <cuda_runtime.h>
#include <cuda_bf16.h>
#include <cstdint>
#include <math.h>

// Problem dims (fixed)
#define BB 1024   // batch
#define SS 128    // seq len
#define VV 20000  // vocab
#define EE 512    // embed dim
#define HH 1024   // hidden
#define GG 4096   // 4*H (gates)
#define KTOT 1536 // E + H
#define NN 4096   // output dim

// Tiling: BM=128, BN=256 -> grid 16x8 = 128 CTAs = ONE WAVE on 148 SMs
#define BM 128
#define BN 256
#define BK 64
#define ROWB 144                          // bytes per smem row (128 data + 16 pad)
#define TILEB_A (BM * ROWB)               // 18432 B
#define TILEB_B (BN * ROWB)               // 36864 B
#define STAGE (2*TILEB_A + 2*TILEB_B)     // Ah|Al|Bh|Bl = 110592 B
#define SMEM_TOTAL (2 * STAGE)            // 221184 B (2-stage double buffer)

typedef __nv_bfloat16 bf16;

// Scratch: everything pre-split into bf16 (hi, lo) pairs
__device__ bf16 g_tabh[(size_t)VV * EE];
__device__ bf16 g_tabl[(size_t)VV * EE];
__device__ bf16 g_wph[(size_t)GG * KTOT];
__device__ bf16 g_wpl[(size_t)GG * KTOT];
__device__ bf16 g_woh[(size_t)NN * HH];
__device__ bf16 g_wol[(size_t)NN * HH];
__device__ float g_biasp[GG];
__device__ bf16 g_hhiA[BB * HH];          // h ping-pong (intra-launch race fix)
__device__ bf16 g_hhiB[BB * HH];
__device__ bf16 g_hloA[BB * HH];
__device__ bf16 g_hloB[BB * HH];
__device__ float g_c[BB * HH];

// ---------------------------------------------------------------------------
__device__ __forceinline__ uint32_t smem_u32(const void* p) {
    uint32_t a;
    asm("{ .reg .u64 t; cvta.to.shared.u64 t, %1; cvt.u32.u64 %0, t; }" : "=r"(a) : "l"(p));
    return a;
}
#define CP16(dst, src) \
    asm volatile("cp.async.cg.shared.global [%0], [%1], 16;" :: "r"(dst), "l"(src))
#define CP_COMMIT() asm volatile("cp.async.commit_group;" ::: "memory")
#define CP_WAIT1()  asm volatile("cp.async.wait_group 1;" ::: "memory")

__device__ __forceinline__ void ldsm4(uint32_t& r0, uint32_t& r1, uint32_t& r2,
                                      uint32_t& r3, uint32_t addr) {
    asm volatile("ldmatrix.sync.aligned.m8n8.x4.shared.b16 {%0,%1,%2,%3}, [%4];"
                 : "=r"(r0), "=r"(r1), "=r"(r2), "=r"(r3) : "r"(addr));
}
__device__ __forceinline__ void ldsm2(uint32_t& r0, uint32_t& r1, uint32_t addr) {
    asm volatile("ldmatrix.sync.aligned.m8n8.x2.shared.b16 {%0,%1}, [%2];"
                 : "=r"(r0), "=r"(r1) : "r"(addr));
}
__device__ __forceinline__ void mma_bf16(float* c, const uint32_t* a, const uint32_t* b) {
    asm volatile(
        "mma.sync.aligned.m16n8k16.row.col.f32.bf16.bf16.f32 "
        "{%0,%1,%2,%3}, {%4,%5,%6,%7}, {%8,%9}, {%0,%1,%2,%3};"
        : "+f"(c[0]), "+f"(c[1]), "+f"(c[2]), "+f"(c[3])
        : "r"(a[0]), "r"(a[1]), "r"(a[2]), "r"(a[3]), "r"(b[0]), "r"(b[1]));
}
__device__ __forceinline__ float fsigmoid(float x) { return 1.0f / (1.0f + expf(-x)); }

// split x into bf16 hi + bf16 lo (≈16 mantissa bits total)
__device__ __forceinline__ void bsplit(float x, bf16& h, bf16& l) {
    h = __float2bfloat16(x);
    l = __float2bfloat16(x - __bfloat162float(h));
}

// ---------------------------------------------------------------------------
// Prep kernels (3 launches before the mainloop so ncu lands on lstm_gemm)
// ---------------------------------------------------------------------------
__global__ void splitTab_kernel(const float* __restrict__ tab) {
    int v = blockIdx.x;
    const float4* s = (const float4*)(tab + (size_t)v * EE);
    float4 val = s[threadIdx.x];
    size_t d = (size_t)v * EE + threadIdx.x * 4;
    bsplit(val.x, g_tabh[d + 0], g_tabl[d + 0]);
    bsplit(val.y, g_tabh[d + 1], g_tabl[d + 1]);
    bsplit(val.z, g_tabh[d + 2], g_tabl[d + 2]);
    bsplit(val.w, g_tabh[d + 3], g_tabl[d + 3]);
}
// Wp[4u+g, :] = [W_ih[g*H+u, :] | W_hh[g*H+u, :]], split bf16 hi/lo
__global__ void permW_kernel(const float* __restrict__ Wih, const float* __restrict__ Whh) {
    int n = blockIdx.x;
    int u = n >> 2, g = n & 3;
    int sr = g * HH + u;
    const float4* s1 = (const float4*)(Wih + (size_t)sr * EE);
    const float4* s2 = (const float4*)(Whh + (size_t)sr * HH);
    size_t base = (size_t)n * KTOT;
    float4 v;
    v = s1[threadIdx.x];
    {   size_t d = base + threadIdx.x * 4;
        bsplit(v.x, g_wph[d+0], g_wpl[d+0]); bsplit(v.y, g_wph[d+1], g_wpl[d+1]);
        bsplit(v.z, g_wph[d+2], g_wpl[d+2]); bsplit(v.w, g_wph[d+3], g_wpl[d+3]); }
    v = s2[threadIdx.x];
    {   size_t d = base + EE + threadIdx.x * 4;
        bsplit(v.x, g_wph[d+0], g_wpl[d+0]); bsplit(v.y, g_wph[d+1], g_wpl[d+1]);
        bsplit(v.z, g_wph[d+2], g_wpl[d+2]); bsplit(v.w, g_wph[d+3], g_wpl[d+3]); }
    v = s2[128 + threadIdx.x];
    {   size_t d = base + EE + 512 + threadIdx.x * 4;
        bsplit(v.x, g_wph[d+0], g_wpl[d+0]); bsplit(v.y, g_wph[d+1], g_wpl[d+1]);
        bsplit(v.z, g_wph[d+2], g_wpl[d+2]); bsplit(v.w, g_wph[d+3], g_wpl[d+3]); }
}
// fused: zero h/c buffers + permuted bias
__global__ void zeroPermB_kernel(const float* __restrict__ bih, const float* __restrict__ bhh) {
    int i = blockIdx.x * blockDim.x + threadIdx.x;
    bf16 z = __float2bfloat16(0.0f);
    g_hhiA[i] = z; g_hhiB[i] = z; g_hloA[i] = z; g_hloB[i] = z;
    g_c[i] = 0.0f;
    if (i < GG) {
        int u = i >> 2, g = i & 3;
        int sr = g * HH + u;
        g_biasp[i] = bih[sr] + bhh[sr];
    }
}
__global__ void splitWout_kernel(const float* __restrict__ Wout) {
    int n = blockIdx.x;
    const float4* s = (const float4*)(Wout + (size_t)n * HH);
    size_t base = (size_t)n * HH;
#pragma unroll
    for (int seg = 0; seg < 2; seg++) {
        float4 v = s[seg * 128 + threadIdx.x];
        size_t d = base + (seg * 128 + threadIdx.x) * 4;
        bsplit(v.x, g_woh[d+0], g_wol[d+0]); bsplit(v.y, g_woh[d+1], g_wol[d+1]);
        bsplit(v.z, g_woh[d+2], g_wol[d+2]); bsplit(v.w, g_woh[d+3], g_wol[d+3]);
    }
}

// ---------------------------------------------------------------------------
// bf16x3 mma.sync GEMM, tile 128x256, 256 threads (8 warps, warp tile 64x64),
// 2-stage cp.async double buffer. Grid = 128 CTAs = one wave.
// CELL=true: A = [emb(m[b,s]) | hIn] (gather fused), LSTM epilogue -> hOut, c.
// ---------------------------------------------------------------------------
template <bool CELL>
__global__ __launch_bounds__(256, 1) void lstm_gemm(
    const int* __restrict__ mPtr, int sStep,
    const bf16* __restrict__ tabh, const bf16* __restrict__ tabl,
    const bf16* __restrict__ A1h, const bf16* __restrict__ A1l, int lda,
    const bf16* __restrict__ Bh,  const bf16* __restrict__ Bl,  int ldb,
    int nIter,
    const float* __restrict__ bias,
    const bf16* __restrict__ hInHi, const bf16* __restrict__ hInLo,
    bf16* __restrict__ hOutHi, bf16* __restrict__ hOutLo,
    float* __restrict__ cPtr,
    float* __restrict__ out)
{
    extern __shared__ __align__(16) char smem[];
    __shared__ int msm[BM];
    const uint32_t sb = smem_u32(smem);
    const int tid  = threadIdx.x;
    const int wid  = tid >> 5, lane = tid & 31;
    const int wm   = wid >> 2;            // 0..1  -> m base 64*wm
    const int wn   = wid & 3;             // 0..3  -> n base 64*wn
    const int row0 = blockIdx.y * BM;
    const int col0 = blockIdx.x * BN;

    if (CELL) {
        if (tid < BM) msm[tid] = mPtr[(size_t)(row0 + tid) * SS + sStep];
        __syncthreads();
    }

    float acc[4][8][4];
#pragma unroll
    for (int i = 0; i < 4; i++)
#pragma unroll
        for (int j = 0; j < 8; j++)
#pragma unroll
            for (int r = 0; r < 4; r++) acc[i][j][r] = 0.0f;

    // stage layout: [Ah | Al | Bh | Bl]
    auto load_stage = [&](int slot, int k0) {
        const uint32_t ah = sb + slot * STAGE;
        const uint32_t al = ah + TILEB_A;
        const uint32_t bh = al + TILEB_A;
        const uint32_t bl = bh + TILEB_B;
#pragma unroll
        for (int j = 0; j < 4; j++) {                  // A: 128 rows x 8 chunks
            int cidx = tid + j * 256;
            int r = cidx >> 3, q = cidx & 7;
            uint32_t soff = (uint32_t)(r * ROWB + q * 16);
            if (CELL) {
                if (k0 < EE) {
                    size_t goff = (size_t)msm[r] * EE + k0 + q * 8;
                    CP16(ah + soff, tabh + goff);
                    CP16(al + soff, tabl + goff);
                } else {
                    size_t goff = (size_t)(row0 + r) * HH + (k0 - EE) + q * 8;
                    CP16(ah + soff, hInHi + goff);
                    CP16(al + soff, hInLo + goff);
                }
            } else {
                size_t goff = (size_t)(row0 + r) * lda + k0 + q * 8;
                CP16(ah + soff, A1h + goff);
                CP16(al + soff, A1l + goff);
            }
        }
#pragma unroll
        for (int j = 0; j < 8; j++) {                  // B: 256 rows x 8 chunks
            int cidx = tid + j * 256;
            int r = cidx >> 3, q = cidx & 7;
            uint32_t soff = (uint32_t)(r * ROWB + q * 16);
            size_t goff = (size_t)(col0 + r) * ldb + k0 + q * 8;
            CP16(bh + soff, Bh + goff);
            CP16(bl + soff, Bl + goff);
        }
    };

    auto compute = [&](int slot) {
        const uint32_t ah = sb + slot * STAGE;
        const uint32_t al = ah + TILEB_A;
        const uint32_t bh = al + TILEB_A;
        const uint32_t bl = bh + TILEB_B;
        const int arow  = wm * 64 + (lane & 15);
        const int acolB = (lane >> 4) * 16;            // byte offset of k-half
        const int brow  = wn * 64 + (lane & 7);
        const int bcolB = ((lane >> 3) & 1) * 16;
#pragma unroll
        for (int ks = 0; ks < 4; ks++) {               // 4 x k16 per BK=64 stage
            const int kB = ks * 32;
            uint32_t afh[4][4], afl[4][4];
#pragma unroll
            for (int mt = 0; mt < 4; mt++) {
                uint32_t off = (uint32_t)((arow + mt * 16) * ROWB + acolB + kB);
                ldsm4(afh[mt][0], afh[mt][1], afh[mt][2], afh[mt][3], ah + off);
                ldsm4(afl[mt][0], afl[mt][1], afl[mt][2], afl[mt][3], al + off);
            }
#pragma unroll
            for (int nt = 0; nt < 8; nt++) {           // B frags loaded per-nt (short live range)
                uint32_t off = (uint32_t)((brow + nt * 8) * ROWB + bcolB + kB);
                uint32_t bfh[2], bfl[2];
                ldsm2(bfh[0], bfh[1], bh + off);
                ldsm2(bfl[0], bfl[1], bl + off);
#pragma unroll
                for (int mt = 0; mt < 4; mt++) {
                    mma_bf16(acc[mt][nt], afh[mt], bfh);   // hi*hi
                    mma_bf16(acc[mt][nt], afl[mt], bfh);   // lo*hi
                    mma_bf16(acc[mt][nt], afh[mt], bfl);   // hi*lo
                }
            }
        }
    };

    // 2-stage pipeline
    load_stage(0, 0); CP_COMMIT();
    for (int it = 0; it < nIter; ++it) {
        if (it + 1 < nIter) load_stage((it + 1) & 1, (it + 1) * BK);
        CP_COMMIT();
        CP_WAIT1();                    // stage it&1 complete (1 outstanding group)
        __syncthreads();
        compute(it & 1);
        __syncthreads();               // protect slot before it is reloaded
    }

    if (CELL) {
        // single-pass epilogue: stage acc into [128][260] floats (133 KB, fits smem)
        float* gsm = (float*)smem;
        const int h0 = col0 >> 2;                      // 64 hidden units per tile
#pragma unroll
        for (int mt = 0; mt < 4; mt++) {
            const int lr = wm * 64 + mt * 16 + (lane >> 2);
#pragma unroll
            for (int nt = 0; nt < 8; nt++) {
                const int cc = wn * 64 + nt * 8 + 2 * (lane & 3);
                float2 v0 = {acc[mt][nt][0], acc[mt][nt][1]};
                float2 v1 = {acc[mt][nt][2], acc[mt][nt][3]};
                *(float2*)&gsm[lr * 260 + cc]       = v0;
                *(float2*)&gsm[(lr + 8) * 260 + cc] = v1;
            }
        }
        __syncthreads();
#pragma unroll
        for (int j = 0; j < 32; j++) {
            const int idx = tid + j * 256;             // 0..8191 = 128 rows x 64 units
            const int lr = idx >> 6, u = idx & 63;
            const float4 g  = *(const float4*)&gsm[lr * 260 + 4 * u];
            const float4 bv = *(const float4*)&bias[col0 + 4 * u];
            const int grow = row0 + lr;
            const size_t off = (size_t)grow * HH + h0 + u;
            const float co = cPtr[off];
            const float gi = fsigmoid(g.x + bv.x);
            const float gf = fsigmoid(g.y + bv.y);
            const float gg = tanhf(g.z + bv.z);
            const float go = fsigmoid(g.w + bv.w);
            const float cn = gf * co + gi * gg;
            const float hn = go * tanhf(cn);
            cPtr[off] = cn;
            bf16 hb = __float2bfloat16(hn);
            hOutHi[off] = hb;
            hOutLo[off] = __float2bfloat16(hn - __bfloat162float(hb));
        }
    } else {
#pragma unroll
        for (int mt = 0; mt < 4; mt++) {
            const int rr = row0 + wm * 64 + mt * 16 + (lane >> 2);
#pragma unroll
            for (int nt = 0; nt < 8; nt++) {
                const int cc = col0 + wn * 64 + nt * 8 + 2 * (lane & 3);
                float2 v0 = {acc[mt][nt][0] + bias[cc], acc[mt][nt][1] + bias[cc + 1]};
                float2 v1 = {acc[mt][nt][2] + bias[cc], acc[mt][nt][3] + bias[cc + 1]};
                *(float2*)(out + (size_t)rr * NN + cc)       = v0;
                *(float2*)(out + (size_t)(rr + 8) * NN + cc) = v1;
            }
        }
    }
}

// ---------------------------------------------------------------------------
extern "C" void kernel_launch(void* const* d_in, const int* in_sizes, int n_in,
                              void* d_out, int out_size) {
    const int*   m     = (const int*)d_in[0];
    const float* tab   = (const float*)d_in[1];
    const float* W_ih  = (const float*)d_in[2];
    const float* W_hh  = (const float*)d_in[3];
    const float* b_ih  = (const float*)d_in[4];
    const float* b_hh  = (const float*)d_in[5];
    const float* W_out = (const float*)d_in[6];
    const float* b_out = (const float*)d_in[7];
    float* out = (float*)d_out;

    bf16 *tabh, *tabl, *wph, *wpl, *woh, *wol;
    float *biasp, *c;
    bf16 *hhi[2], *hlo[2];
    cudaGetSymbolAddress((void**)&tabh,    g_tabh);
    cudaGetSymbolAddress((void**)&tabl,    g_tabl);
    cudaGetSymbolAddress((void**)&wph,     g_wph);
    cudaGetSymbolAddress((void**)&wpl,     g_wpl);
    cudaGetSymbolAddress((void**)&woh,     g_woh);
    cudaGetSymbolAddress((void**)&wol,     g_wol);
    cudaGetSymbolAddress((void**)&biasp,   g_biasp);
    cudaGetSymbolAddress((void**)&hhi[0],  g_hhiA);
    cudaGetSymbolAddress((void**)&hhi[1],  g_hhiB);
    cudaGetSymbolAddress((void**)&hlo[0],  g_hloA);
    cudaGetSymbolAddress((void**)&hlo[1],  g_hloB);
    cudaGetSymbolAddress((void**)&c,       g_c);

    cudaFuncSetAttribute(lstm_gemm<true>,  cudaFuncAttributeMaxDynamicSharedMemorySize, SMEM_TOTAL);
    cudaFuncSetAttribute(lstm_gemm<false>, cudaFuncAttributeMaxDynamicSharedMemorySize, SMEM_TOTAL);

    // prep: exactly 3 launches before the mainloop so ncu lands on lstm_gemm
    splitTab_kernel<<<VV, 128>>>(tab);
    permW_kernel<<<GG, 128>>>(W_ih, W_hh);
    zeroPermB_kernel<<<(BB * HH) / 256, 256>>>(b_ih, b_hh);

    dim3 grid(NN / BN, BB / BM);   // (16, 8) = 128 CTAs -> single wave
    for (int s = 0; s < SS; s++) {
        const int rd = s & 1, wr = (s + 1) & 1;   // ping-pong h (race fix)
        lstm_gemm<true><<<grid, 256, SMEM_TOTAL>>>(
            m, s, tabh, tabl,
            nullptr, nullptr, 0,
            wph, wpl, KTOT,
            KTOT / BK,              // 24 iters
            biasp,
            hhi[rd], hlo[rd],       // read h_s
            hhi[wr], hlo[wr],       // write h_{s+1}
            c, nullptr);
    }
    // W_out split only needed now
    splitWout_kernel<<<NN, 128>>>(W_out);
    // after 128 steps (even), final h is in buffer 0
    lstm_gemm<false><<<grid, 256, SMEM_TOTAL>>>(
        nullptr, 0, nullptr, nullptr,
        hhi[0], hlo[0], HH,
        woh, wol, HH,
        HH / BK,                    // 16 iters
        b_out,
        nullptr, nullptr, nullptr, nullptr, nullptr, out);
}